// round 14
// baseline (speedup 1.0000x reference)
#include <cuda_runtime.h>
#include <cuda_fp16.h>
#include <math.h>
#include <stdint.h>

#define HW    56
#define NPIX  3136
#define CDIM  256
#define HEADS 8
#define HD    32
#define NPAIR 16
#define BATCH 2
#define MROWS (BATCH*NPIX)
#define WIN   7
#define RAD   3

__device__ __half g_vh[BATCH*HEADS*NPIX*HD];
__device__ __half g_qh[BATCH*HEADS*NPIX*HD];   // pre-scaled by 1/sqrt(32)
__device__ __half g_kh[BATCH*HEADS*NPIX*HD];
__device__ float  g_cos[NPIX*NPAIR];
__device__ float  g_sin[NPIX*NPAIR];
__device__ __half g_Xh[MROWS*CDIM];
__device__ __half g_Wqt[768*CDIM];
__device__ __half g_Wpt[CDIM*CDIM];
__device__ __half g_attn[MROWS*CDIM];

// ---------- prep ----------
#define SEG0 (NPIX*NPAIR)
#define SEG1 (SEG0 + MROWS*CDIM)
#define SEG2 (SEG1 + 768*CDIM)
#define SEG3 (SEG2 + CDIM*CDIM)

__global__ void prep_kernel(const float* __restrict__ X, const float* __restrict__ Wq,
                            const float* __restrict__ Wp) {
    int idx = blockIdx.x * 256 + threadIdx.x;
    if (idx < SEG0) {
        int p = idx & 15, n = idx >> 4;
        double inv = pow(10000.0, -(double)p / 16.0);
        double s, c;
        sincos((double)n * inv, &s, &c);
        g_cos[idx] = (float)c; g_sin[idx] = (float)s;
    } else if (idx < SEG1) {
        int j = idx - SEG0;
        g_Xh[j] = __float2half(X[j]);
    } else if (idx < SEG2) {
        int j = idx - SEG1;
        int n = j >> 8, k = j & 255;
        g_Wqt[j] = __float2half(Wq[k * 768 + n]);
    } else if (idx < SEG3) {
        int j = idx - SEG2;
        int n = j >> 8, k = j & 255;
        g_Wpt[j] = __float2half(Wp[k * 256 + n]);
    }
}

// ---------- mma helpers ----------
__device__ __forceinline__ void ldmatrix_x4(uint32_t* r, uint32_t addr) {
    asm volatile("ldmatrix.sync.aligned.m8n8.x4.shared.b16 {%0,%1,%2,%3}, [%4];"
                 : "=r"(r[0]), "=r"(r[1]), "=r"(r[2]), "=r"(r[3]) : "r"(addr));
}
__device__ __forceinline__ void mma16816(float* c, const uint32_t* a, uint32_t b0, uint32_t b1) {
    asm volatile("mma.sync.aligned.m16n8k16.row.col.f32.f16.f16.f32 "
                 "{%0,%1,%2,%3}, {%4,%5,%6,%7}, {%8,%9}, {%0,%1,%2,%3};"
                 : "+f"(c[0]), "+f"(c[1]), "+f"(c[2]), "+f"(c[3])
                 : "r"(a[0]), "r"(a[1]), "r"(a[2]), "r"(a[3]), "r"(b0), "r"(b1));
}
__device__ __forceinline__ void cp_async16(uint32_t dst, const void* src) {
    asm volatile("cp.async.cg.shared.global [%0], [%1], 16;" :: "r"(dst), "l"(src));
}
__device__ __forceinline__ void cp_commit() { asm volatile("cp.async.commit_group;"); }
template<int N> __device__ __forceinline__ void cp_wait() {
    asm volatile("cp.async.wait_group %0;" :: "n"(N) : "memory");
}

// ---------- GEMM: D[128x64] = A[128x256] @ B[64x256]^T, fp16 ----------
// 128 threads, 4 warps (2x2), warp tile 64x32. 4-stage pipeline = entire K resident.
#define A_TILE_B 18432                  // 128 x 72 halves
#define STAGE_B  27648                  // + 64 x 72 halves
#define GEMM_SMEM (4*STAGE_B)           // 110592

__global__ void __launch_bounds__(128) gemm_mma(int mode, const float* __restrict__ bias,
                                                float* __restrict__ out) {
    extern __shared__ __align__(16) __half smg[];
    const uint32_t sb = (uint32_t)__cvta_generic_to_shared(smg);

    const int tid = threadIdx.x, wid = tid >> 5, lane = tid & 31;
    const int warp_m = wid & 1, warp_n = wid >> 1;       // 2 x 2 warps
    const int mBase = blockIdx.y * 128, nBase = blockIdx.x * 64;

    const __half* A = mode ? g_attn : g_Xh;
    const __half* B = mode ? g_Wpt  : g_Wqt;

    float acc[4][4][4];
#pragma unroll
    for (int i = 0; i < 4; i++)
#pragma unroll
        for (int j = 0; j < 4; j++)
#pragma unroll
            for (int k = 0; k < 4; k++) acc[i][j][k] = 0.f;

    uint32_t aoff[4], boff[2];
#pragma unroll
    for (int mi = 0; mi < 4; mi++)
        aoff[mi] = (uint32_t)(((warp_m * 64 + mi * 16 + (lane & 15)) * 72 + ((lane >> 4) << 3)) * 2);
#pragma unroll
    for (int np = 0; np < 2; np++)
        boff[np] = (uint32_t)(((warp_n * 32 + np * 16 + ((lane >> 4) << 3) + (lane & 7)) * 72 +
                               (((lane >> 3) & 1) << 3)) * 2);

    const int lkc = (tid & 7) << 3;

    auto issue = [&](int c) {
        const uint32_t s0 = sb + (uint32_t)c * STAGE_B;
        const int kb = c * 64 + lkc;
#pragma unroll
        for (int t = 0; t < 8; t++) {
            int r = (t * 128 + tid) >> 3;
            cp_async16(s0 + (uint32_t)((r * 72 + lkc) * 2),
                       A + (size_t)(mBase + r) * 256 + kb);
        }
#pragma unroll
        for (int t = 0; t < 4; t++) {
            int r = (t * 128 + tid) >> 3;
            cp_async16(s0 + A_TILE_B + (uint32_t)((r * 72 + lkc) * 2),
                       B + (size_t)(nBase + r) * 256 + kb);
        }
        cp_commit();
    };

    issue(0); issue(1); issue(2); issue(3);

#pragma unroll
    for (int c = 0; c < 4; c++) {
        if (c == 0) cp_wait<3>(); else if (c == 1) cp_wait<2>();
        else if (c == 2) cp_wait<1>(); else cp_wait<0>();
        __syncthreads();

        const uint32_t su = sb + (uint32_t)c * STAGE_B;
#pragma unroll
        for (int kk = 0; kk < 4; kk++) {
            const uint32_t ko = kk * 32;
            uint32_t a[4][4], b[2][4];
#pragma unroll
            for (int mi = 0; mi < 4; mi++) ldmatrix_x4(a[mi], su + aoff[mi] + ko);
#pragma unroll
            for (int np = 0; np < 2; np++) ldmatrix_x4(b[np], su + A_TILE_B + boff[np] + ko);
#pragma unroll
            for (int mi = 0; mi < 4; mi++)
#pragma unroll
                for (int ni = 0; ni < 4; ni++)
                    mma16816(acc[mi][ni], a[mi], b[ni >> 1][(ni & 1) * 2], b[ni >> 1][(ni & 1) * 2 + 1]);
        }
    }

    // ---- epilogue ----
    const float qscale = 0.17677669529663688f;
#pragma unroll
    for (int mi = 0; mi < 4; mi++) {
#pragma unroll
        for (int half = 0; half < 2; half++) {
            int grow = mBase + warp_m * 64 + mi * 16 + (lane >> 2) + half * 8;
            int b = (grow >= NPIX) ? 1 : 0;
            int nr = grow - b * NPIX;
            if (mode == 0) {
#pragma unroll
                for (int ni = 0; ni < 4; ni++) {
                    int gc = nBase + warp_n * 32 + ni * 8 + (lane & 3) * 2;
                    float x0 = acc[mi][ni][half * 2], x1 = acc[mi][ni][half * 2 + 1];
                    int which = gc >> 8;
                    int head = (gc >> 5) & 7;
                    int d0 = gc & 31;
                    size_t base = ((size_t)(b * HEADS + head) * NPIX + nr) * HD + d0;
                    if (which < 2) {
                        int p = d0 >> 1;
                        float cv = g_cos[nr * NPAIR + p], sv = g_sin[nr * NPAIR + p];
                        float o0 = x0 * cv - x1 * sv;
                        float o1 = x1 * cv + x0 * sv;
                        if (which == 0) {
                            *(__half2*)&g_qh[base] = __floats2half2_rn(o0 * qscale, o1 * qscale);
                        } else {
                            *(__half2*)&g_kh[base] = __floats2half2_rn(o0, o1);
                        }
                    } else {
                        *(__half2*)&g_vh[base] = __floats2half2_rn(x0, x1);
                    }
                }
            } else {
#pragma unroll
                for (int ni = 0; ni < 4; ni++) {
                    int gc = nBase + warp_n * 32 + ni * 8 + (lane & 3) * 2;
                    float2 bv = *(const float2*)&bias[gc];
                    *(float2*)&out[(size_t)grow * 256 + gc] =
                        make_float2(acc[mi][ni][half * 2] + bv.x,
                                    acc[mi][ni][half * 2 + 1] + bv.y);
                }
            }
        }
    }
}

// ---------- attention: mma scores + fp32 softmax + smem-half V (R13, unchanged) ----------
#define KH_OFF 0
#define SP_OFF 35840
#define QS_OFF 47488
#define VS_OFF 57728
#define ATTN_SMEM 82816

__global__ void __launch_bounds__(256, 2) attn_kernel() {
    extern __shared__ __align__(16) char smc[];
    const uint32_t sbase = (uint32_t)__cvta_generic_to_shared(smc);
    __half* kh = (__half*)(smc + KH_OFF);
    float*  sp = (float*)(smc + SP_OFF);
    __half* qs = (__half*)(smc + QS_OFF);
    __half* vs = (__half*)(smc + VS_OFF);

    const int i  = blockIdx.x;
    const int bh = blockIdx.y;
    const int tid = threadIdx.x, w = tid >> 5, lane = tid & 31;
    const int r0 = min(max(i - RAD, 0), HW - WIN);

    const __half* gk = g_kh + ((size_t)bh * NPIX + r0 * HW) * HD;
    for (int idx = tid; idx < 7 * 56 * 4; idx += 256) {
        int r = idx / 224, rem = idx - r * 224;
        int c = rem >> 2, d8 = (rem & 3) << 3;
        *(uint4*)&kh[(r * 64 + c) * 40 + d8] = *(const uint4*)(gk + (r * 56 + c) * 32 + d8);
    }
    const __half* gvh = g_vh + ((size_t)bh * NPIX + r0 * HW) * HD;
    for (int idx = tid; idx < 7 * 56 * 4; idx += 256) {
        ((uint4*)vs)[idx] = ((const uint4*)gvh)[idx];
    }
    const __half* gq = g_qh + ((size_t)bh * NPIX + i * HW) * HD;
    for (int idx = tid; idx < 56 * 4; idx += 256) {
        int j = idx >> 2, d8 = (idx & 3) << 3;
        int row = (j / 7) * 16 + (j % 7);
        *(uint4*)&qs[row * 40 + d8] = *(const uint4*)(gq + j * 32 + d8);
    }
    __syncthreads();

    const int j0 = w * 7;
    const int cbase = min(max(j0 - RAD, 0), HW - WIN);

    uint32_t A0[4], A1[4];
    {
        uint32_t qaddr = sbase + QS_OFF +
            (uint32_t)(((w * 16 + (lane & 15)) * 40 + ((lane >> 4) << 3)) * 2);
        ldmatrix_x4(A0, qaddr);
        ldmatrix_x4(A1, qaddr + 32);
    }
    const int qr = lane >> 2;

#pragma unroll
    for (int r = 0; r < 7; r++) {
#pragma unroll
        for (int nt = 0; nt < 2; nt++) {
            uint32_t b[4];
            uint32_t kaddr = sbase + KH_OFF +
                (uint32_t)((((r * 64 + cbase + nt * 8 + (lane & 7)) * 40 + ((lane >> 3) << 3)) * 2));
            ldmatrix_x4(b, kaddr);
            float c4[4] = {0.f, 0.f, 0.f, 0.f};
            mma16816(c4, A0, b[0], b[1]);
            mma16816(c4, A1, b[2], b[3]);
            if (qr < 7) {
                int j = j0 + qr;
                int c0j = min(max(j - RAD, 0), HW - WIN);
#pragma unroll
                for (int e = 0; e < 2; e++) {
                    int key = cbase + nt * 8 + (lane & 3) * 2 + e;
                    int kc = key - c0j;
                    if (kc >= 0 && kc < 7)
                        sp[j * 52 + r * 7 + kc] = c4[e];
                }
            }
        }
    }
    __syncwarp();

    const int b = bh >> 3, h = bh & 7;
    const bool has1 = (lane < 17);

    for (int t = 0; t < 7; t++) {
        const int j = j0 + t;
        const int c0j = min(max(j - RAD, 0), HW - WIN);

        float s0 = sp[j * 52 + lane];
        float s1 = has1 ? sp[j * 52 + 32 + lane] : -1e30f;

        float mx = fmaxf(s0, s1);
        mx = fmaxf(mx, __shfl_xor_sync(0xffffffffu, mx, 16));
        mx = fmaxf(mx, __shfl_xor_sync(0xffffffffu, mx, 8));
        mx = fmaxf(mx, __shfl_xor_sync(0xffffffffu, mx, 4));
        mx = fmaxf(mx, __shfl_xor_sync(0xffffffffu, mx, 2));
        mx = fmaxf(mx, __shfl_xor_sync(0xffffffffu, mx, 1));

        float p0 = __expf(s0 - mx);
        float p1 = has1 ? __expf(s1 - mx) : 0.f;
        float ls = p0 + p1;
        ls += __shfl_xor_sync(0xffffffffu, ls, 16);
        ls += __shfl_xor_sync(0xffffffffu, ls, 8);
        ls += __shfl_xor_sync(0xffffffffu, ls, 4);
        ls += __shfl_xor_sync(0xffffffffu, ls, 2);
        ls += __shfl_xor_sync(0xffffffffu, ls, 1);
        float inv = 1.0f / ls;

        sp[j * 52 + lane] = p0 * inv;
        if (has1) sp[j * 52 + 32 + lane] = p1 * inv;
        __syncwarp();

        float o = 0.f;
#pragma unroll
        for (int rr = 0; rr < 7; rr++) {
            const __half* vrow = vs + (rr * HW + c0j) * HD + lane;
            const float* prow = sp + j * 52 + rr * 7;
#pragma unroll
            for (int cc = 0; cc < 7; cc++) {
                o = fmaf(prow[cc], __half2float(vrow[cc * HD]), o);
            }
        }
        size_t oi = ((size_t)b * NPIX + i * HW + j) * CDIM + h * HD + lane;
        g_attn[oi] = __float2half(o);
        __syncwarp();
    }
}

// ---------- launch ----------
extern "C" void kernel_launch(void* const* d_in, const int* in_sizes, int n_in,
                              void* d_out, int out_size) {
    const float* x     = (const float*)d_in[0];
    const float* Wqkv  = (const float*)d_in[1];
    const float* Wproj = (const float*)d_in[2];
    const float* bproj = (const float*)d_in[3];
    float* out = (float*)d_out;

    static bool attr_set = false;
    if (!attr_set) {
        cudaFuncSetAttribute(gemm_mma, cudaFuncAttributeMaxDynamicSharedMemorySize, GEMM_SMEM);
        cudaFuncSetAttribute(attn_kernel, cudaFuncAttributeMaxDynamicSharedMemorySize, ATTN_SMEM);
        attr_set = true;
    }

    prep_kernel<<<(SEG3 + 255) / 256, 256>>>(x, Wqkv, Wproj);
    gemm_mma<<<dim3(12, 49), 128, GEMM_SMEM>>>(0, bproj, out);
    attn_kernel<<<dim3(HW, BATCH * HEADS), 256, ATTN_SMEM>>>();
    gemm_mma<<<dim3(4, 49), 128, GEMM_SMEM>>>(1, bproj, out);
}

// round 15
// speedup vs baseline: 1.0044x; 1.0044x over previous
#include <cuda_runtime.h>
#include <cuda_fp16.h>
#include <math.h>
#include <stdint.h>

#define HW    56
#define NPIX  3136
#define CDIM  256
#define HEADS 8
#define HD    32
#define NPAIR 16
#define BATCH 2
#define MROWS (BATCH*NPIX)
#define WIN   7
#define RAD   3

__device__ __half g_vh[BATCH*HEADS*NPIX*HD];
__device__ __half g_qh[BATCH*HEADS*NPIX*HD];   // pre-scaled by 1/sqrt(32)
__device__ __half g_kh[BATCH*HEADS*NPIX*HD];
__device__ float  g_cos[NPIX*NPAIR];
__device__ float  g_sin[NPIX*NPAIR];
__device__ __half g_Xh[MROWS*CDIM];
__device__ __half g_Wqt[768*CDIM];
__device__ __half g_Wpt[CDIM*CDIM];
__device__ __half g_attn[MROWS*CDIM];

// ---------- prep ----------
#define SEG0 (NPIX*NPAIR)
#define SEG1 (SEG0 + MROWS*CDIM)
#define SEG2 (SEG1 + 768*CDIM)
#define SEG3 (SEG2 + CDIM*CDIM)

__global__ void prep_kernel(const float* __restrict__ X, const float* __restrict__ Wq,
                            const float* __restrict__ Wp) {
    int idx = blockIdx.x * 256 + threadIdx.x;
    if (idx < SEG0) {
        int p = idx & 15, n = idx >> 4;
        double inv = pow(10000.0, -(double)p / 16.0);
        double s, c;
        sincos((double)n * inv, &s, &c);
        g_cos[idx] = (float)c; g_sin[idx] = (float)s;
    } else if (idx < SEG1) {
        int j = idx - SEG0;
        g_Xh[j] = __float2half(X[j]);
    } else if (idx < SEG2) {
        int j = idx - SEG1;
        int n = j >> 8, k = j & 255;
        g_Wqt[j] = __float2half(Wq[k * 768 + n]);
    } else if (idx < SEG3) {
        int j = idx - SEG2;
        int n = j >> 8, k = j & 255;
        g_Wpt[j] = __float2half(Wp[k * 256 + n]);
    }
}

// ---------- mma helpers ----------
__device__ __forceinline__ void ldmatrix_x4(uint32_t* r, uint32_t addr) {
    asm volatile("ldmatrix.sync.aligned.m8n8.x4.shared.b16 {%0,%1,%2,%3}, [%4];"
                 : "=r"(r[0]), "=r"(r[1]), "=r"(r[2]), "=r"(r[3]) : "r"(addr));
}
__device__ __forceinline__ void mma16816(float* c, const uint32_t* a, uint32_t b0, uint32_t b1) {
    asm volatile("mma.sync.aligned.m16n8k16.row.col.f32.f16.f16.f32 "
                 "{%0,%1,%2,%3}, {%4,%5,%6,%7}, {%8,%9}, {%0,%1,%2,%3};"
                 : "+f"(c[0]), "+f"(c[1]), "+f"(c[2]), "+f"(c[3])
                 : "r"(a[0]), "r"(a[1]), "r"(a[2]), "r"(a[3]), "r"(b0), "r"(b1));
}
__device__ __forceinline__ void cp_async16(uint32_t dst, const void* src) {
    asm volatile("cp.async.cg.shared.global [%0], [%1], 16;" :: "r"(dst), "l"(src));
}
__device__ __forceinline__ void cp_commit() { asm volatile("cp.async.commit_group;"); }
template<int N> __device__ __forceinline__ void cp_wait() {
    asm volatile("cp.async.wait_group %0;" :: "n"(N) : "memory");
}

// ---------- GEMM: D[128x128] = A[128x256] @ B[128x256]^T, fp16, 4-stage full-K ----------
#define A_TILE_B 18432                  // 128 x 72 halves
#define STAGE_B  36864                  // A + B tiles
#define GEMM_SMEM (4*STAGE_B)           // 147456

__global__ void __launch_bounds__(256) gemm_mma(int mode, const float* __restrict__ bias,
                                                float* __restrict__ out) {
    extern __shared__ __align__(16) __half smg[];
    const uint32_t sb = (uint32_t)__cvta_generic_to_shared(smg);

    const int tid = threadIdx.x, wid = tid >> 5, lane = tid & 31;
    const int warp_m = wid & 3, warp_n = wid >> 2;       // 4 x 2 warps, 32x64 warp tile
    const int mBase = blockIdx.y * 128, nBase = blockIdx.x * 128;

    const __half* A = mode ? g_attn : g_Xh;
    const __half* B = mode ? g_Wpt  : g_Wqt;

    float acc[2][8][4];
#pragma unroll
    for (int i = 0; i < 2; i++)
#pragma unroll
        for (int j = 0; j < 8; j++)
#pragma unroll
            for (int k = 0; k < 4; k++) acc[i][j][k] = 0.f;

    uint32_t aoff[2], boff[4];
#pragma unroll
    for (int mi = 0; mi < 2; mi++)
        aoff[mi] = (uint32_t)(((warp_m * 32 + mi * 16 + (lane & 15)) * 72 + ((lane >> 4) << 3)) * 2);
#pragma unroll
    for (int np = 0; np < 4; np++)
        boff[np] = (uint32_t)(((warp_n * 64 + np * 16 + ((lane >> 4) << 3) + (lane & 7)) * 72 +
                               (((lane >> 3) & 1) << 3)) * 2);

    const int lkc = (tid & 7) << 3;

    auto issue = [&](int c) {
        const uint32_t s0 = sb + (uint32_t)c * STAGE_B;
        const int kb = c * 64 + lkc;
#pragma unroll
        for (int t = 0; t < 4; t++) {
            int r = (t * 256 + tid) >> 3;
            cp_async16(s0 + (uint32_t)((r * 72 + lkc) * 2),
                       A + (size_t)(mBase + r) * 256 + kb);
            cp_async16(s0 + A_TILE_B + (uint32_t)((r * 72 + lkc) * 2),
                       B + (size_t)(nBase + r) * 256 + kb);
        }
        cp_commit();
    };

    issue(0); issue(1); issue(2); issue(3);

#pragma unroll
    for (int c = 0; c < 4; c++) {
        if (c == 0) cp_wait<3>(); else if (c == 1) cp_wait<2>();
        else if (c == 2) cp_wait<1>(); else cp_wait<0>();
        __syncthreads();

        const uint32_t su = sb + (uint32_t)c * STAGE_B;
#pragma unroll
        for (int kk = 0; kk < 4; kk++) {
            const uint32_t ko = kk * 32;
            uint32_t a[2][4], b[4][4];
#pragma unroll
            for (int mi = 0; mi < 2; mi++) ldmatrix_x4(a[mi], su + aoff[mi] + ko);
#pragma unroll
            for (int np = 0; np < 4; np++) ldmatrix_x4(b[np], su + A_TILE_B + boff[np] + ko);
#pragma unroll
            for (int mi = 0; mi < 2; mi++)
#pragma unroll
                for (int ni = 0; ni < 8; ni++)
                    mma16816(acc[mi][ni], a[mi], b[ni >> 1][(ni & 1) * 2], b[ni >> 1][(ni & 1) * 2 + 1]);
        }
    }

    // ---- epilogue ----
    const float qscale = 0.17677669529663688f;
#pragma unroll
    for (int mi = 0; mi < 2; mi++) {
#pragma unroll
        for (int half = 0; half < 2; half++) {
            int grow = mBase + warp_m * 32 + mi * 16 + (lane >> 2) + half * 8;
            int b = (grow >= NPIX) ? 1 : 0;
            int nr = grow - b * NPIX;
            if (mode == 0) {
#pragma unroll
                for (int ni = 0; ni < 8; ni++) {
                    int gc = nBase + warp_n * 64 + ni * 8 + (lane & 3) * 2;
                    float x0 = acc[mi][ni][half * 2], x1 = acc[mi][ni][half * 2 + 1];
                    int which = gc >> 8;
                    int head = (gc >> 5) & 7;
                    int d0 = gc & 31;
                    size_t base = ((size_t)(b * HEADS + head) * NPIX + nr) * HD + d0;
                    if (which < 2) {
                        int p = d0 >> 1;
                        float cv = g_cos[nr * NPAIR + p], sv = g_sin[nr * NPAIR + p];
                        float o0 = x0 * cv - x1 * sv;
                        float o1 = x1 * cv + x0 * sv;
                        if (which == 0) {
                            *(__half2*)&g_qh[base] = __floats2half2_rn(o0 * qscale, o1 * qscale);
                        } else {
                            *(__half2*)&g_kh[base] = __floats2half2_rn(o0, o1);
                        }
                    } else {
                        *(__half2*)&g_vh[base] = __floats2half2_rn(x0, x1);
                    }
                }
            } else {
#pragma unroll
                for (int ni = 0; ni < 8; ni++) {
                    int gc = nBase + warp_n * 64 + ni * 8 + (lane & 3) * 2;
                    float2 bv = *(const float2*)&bias[gc];
                    *(float2*)&out[(size_t)grow * 256 + gc] =
                        make_float2(acc[mi][ni][half * 2] + bv.x,
                                    acc[mi][ni][half * 2 + 1] + bv.y);
                }
            }
        }
    }
}

// ---------- attention: mma scores + fp32 softmax + smem-half V (R13, unchanged) ----------
#define KH_OFF 0
#define SP_OFF 35840
#define QS_OFF 47488
#define VS_OFF 57728
#define ATTN_SMEM 82816

__global__ void __launch_bounds__(256, 2) attn_kernel() {
    extern __shared__ __align__(16) char smc[];
    const uint32_t sbase = (uint32_t)__cvta_generic_to_shared(smc);
    __half* kh = (__half*)(smc + KH_OFF);
    float*  sp = (float*)(smc + SP_OFF);
    __half* qs = (__half*)(smc + QS_OFF);
    __half* vs = (__half*)(smc + VS_OFF);

    const int i  = blockIdx.x;
    const int bh = blockIdx.y;
    const int tid = threadIdx.x, w = tid >> 5, lane = tid & 31;
    const int r0 = min(max(i - RAD, 0), HW - WIN);

    const __half* gk = g_kh + ((size_t)bh * NPIX + r0 * HW) * HD;
    for (int idx = tid; idx < 7 * 56 * 4; idx += 256) {
        int r = idx / 224, rem = idx - r * 224;
        int c = rem >> 2, d8 = (rem & 3) << 3;
        *(uint4*)&kh[(r * 64 + c) * 40 + d8] = *(const uint4*)(gk + (r * 56 + c) * 32 + d8);
    }
    const __half* gvh = g_vh + ((size_t)bh * NPIX + r0 * HW) * HD;
    for (int idx = tid; idx < 7 * 56 * 4; idx += 256) {
        ((uint4*)vs)[idx] = ((const uint4*)gvh)[idx];
    }
    const __half* gq = g_qh + ((size_t)bh * NPIX + i * HW) * HD;
    for (int idx = tid; idx < 56 * 4; idx += 256) {
        int j = idx >> 2, d8 = (idx & 3) << 3;
        int row = (j / 7) * 16 + (j % 7);
        *(uint4*)&qs[row * 40 + d8] = *(const uint4*)(gq + j * 32 + d8);
    }
    __syncthreads();

    const int j0 = w * 7;
    const int cbase = min(max(j0 - RAD, 0), HW - WIN);

    uint32_t A0[4], A1[4];
    {
        uint32_t qaddr = sbase + QS_OFF +
            (uint32_t)(((w * 16 + (lane & 15)) * 40 + ((lane >> 4) << 3)) * 2);
        ldmatrix_x4(A0, qaddr);
        ldmatrix_x4(A1, qaddr + 32);
    }
    const int qr = lane >> 2;

#pragma unroll
    for (int r = 0; r < 7; r++) {
#pragma unroll
        for (int nt = 0; nt < 2; nt++) {
            uint32_t b[4];
            uint32_t kaddr = sbase + KH_OFF +
                (uint32_t)((((r * 64 + cbase + nt * 8 + (lane & 7)) * 40 + ((lane >> 3) << 3)) * 2));
            ldmatrix_x4(b, kaddr);
            float c4[4] = {0.f, 0.f, 0.f, 0.f};
            mma16816(c4, A0, b[0], b[1]);
            mma16816(c4, A1, b[2], b[3]);
            if (qr < 7) {
                int j = j0 + qr;
                int c0j = min(max(j - RAD, 0), HW - WIN);
#pragma unroll
                for (int e = 0; e < 2; e++) {
                    int key = cbase + nt * 8 + (lane & 3) * 2 + e;
                    int kc = key - c0j;
                    if (kc >= 0 && kc < 7)
                        sp[j * 52 + r * 7 + kc] = c4[e];
                }
            }
        }
    }
    __syncwarp();

    const int b = bh >> 3, h = bh & 7;
    const bool has1 = (lane < 17);

    for (int t = 0; t < 7; t++) {
        const int j = j0 + t;
        const int c0j = min(max(j - RAD, 0), HW - WIN);

        float s0 = sp[j * 52 + lane];
        float s1 = has1 ? sp[j * 52 + 32 + lane] : -1e30f;

        float mx = fmaxf(s0, s1);
        mx = fmaxf(mx, __shfl_xor_sync(0xffffffffu, mx, 16));
        mx = fmaxf(mx, __shfl_xor_sync(0xffffffffu, mx, 8));
        mx = fmaxf(mx, __shfl_xor_sync(0xffffffffu, mx, 4));
        mx = fmaxf(mx, __shfl_xor_sync(0xffffffffu, mx, 2));
        mx = fmaxf(mx, __shfl_xor_sync(0xffffffffu, mx, 1));

        float p0 = __expf(s0 - mx);
        float p1 = has1 ? __expf(s1 - mx) : 0.f;
        float ls = p0 + p1;
        ls += __shfl_xor_sync(0xffffffffu, ls, 16);
        ls += __shfl_xor_sync(0xffffffffu, ls, 8);
        ls += __shfl_xor_sync(0xffffffffu, ls, 4);
        ls += __shfl_xor_sync(0xffffffffu, ls, 2);
        ls += __shfl_xor_sync(0xffffffffu, ls, 1);
        float inv = 1.0f / ls;

        sp[j * 52 + lane] = p0 * inv;
        if (has1) sp[j * 52 + 32 + lane] = p1 * inv;
        __syncwarp();

        float o = 0.f;
#pragma unroll
        for (int rr = 0; rr < 7; rr++) {
            const __half* vrow = vs + (rr * HW + c0j) * HD + lane;
            const float* prow = sp + j * 52 + rr * 7;
#pragma unroll
            for (int cc = 0; cc < 7; cc++) {
                o = fmaf(prow[cc], __half2float(vrow[cc * HD]), o);
            }
        }
        size_t oi = ((size_t)b * NPIX + i * HW + j) * CDIM + h * HD + lane;
        g_attn[oi] = __float2half(o);
        __syncwarp();
    }
}

// ---------- launch ----------
extern "C" void kernel_launch(void* const* d_in, const int* in_sizes, int n_in,
                              void* d_out, int out_size) {
    const float* x     = (const float*)d_in[0];
    const float* Wqkv  = (const float*)d_in[1];
    const float* Wproj = (const float*)d_in[2];
    const float* bproj = (const float*)d_in[3];
    float* out = (float*)d_out;

    static bool attr_set = false;
    if (!attr_set) {
        cudaFuncSetAttribute(gemm_mma, cudaFuncAttributeMaxDynamicSharedMemorySize, GEMM_SMEM);
        cudaFuncSetAttribute(attn_kernel, cudaFuncAttributeMaxDynamicSharedMemorySize, ATTN_SMEM);
        attr_set = true;
    }

    prep_kernel<<<(SEG3 + 255) / 256, 256>>>(x, Wqkv, Wproj);
    gemm_mma<<<dim3(6, 49), 256, GEMM_SMEM>>>(0, bproj, out);
    attn_kernel<<<dim3(HW, BATCH * HEADS), 256, ATTN_SMEM>>>();
    gemm_mma<<<dim3(2, 49), 256, GEMM_SMEM>>>(1, bproj, out);
}

// round 17
// speedup vs baseline: 1.0832x; 1.0785x over previous
#include <cuda_runtime.h>
#include <cuda_fp16.h>
#include <math.h>
#include <stdint.h>

#define HW    56
#define NPIX  3136
#define CDIM  256
#define HEADS 8
#define HD    32
#define NPAIR 16
#define BATCH 2
#define MROWS (BATCH*NPIX)
#define WIN   7
#define RAD   3

__device__ __half g_vh[BATCH*HEADS*NPIX*HD];
__device__ __half g_qh[BATCH*HEADS*NPIX*HD];   // pre-scaled by 1/sqrt(32)
__device__ __half g_kh[BATCH*HEADS*NPIX*HD];
__device__ float  g_cos[NPIX*NPAIR];
__device__ float  g_sin[NPIX*NPAIR];
__device__ __half g_Xh[MROWS*CDIM];
__device__ __half g_Wqt[768*CDIM];
__device__ __half g_Wpt[CDIM*CDIM];
__device__ __half g_attn[MROWS*CDIM];

// ---------- prep ----------
#define SEG0 (NPIX*NPAIR)
#define SEG1 (SEG0 + MROWS*CDIM)
#define SEG2 (SEG1 + 768*CDIM)
#define SEG3 (SEG2 + CDIM*CDIM)

__global__ void prep_kernel(const float* __restrict__ X, const float* __restrict__ Wq,
                            const float* __restrict__ Wp) {
    int idx = blockIdx.x * 256 + threadIdx.x;
    if (idx < SEG0) {
        int p = idx & 15, n = idx >> 4;
        double inv = pow(10000.0, -(double)p / 16.0);
        double s, c;
        sincos((double)n * inv, &s, &c);
        g_cos[idx] = (float)c; g_sin[idx] = (float)s;
    } else if (idx < SEG1) {
        int j = idx - SEG0;
        g_Xh[j] = __float2half(X[j]);
    } else if (idx < SEG2) {
        int j = idx - SEG1;
        int n = j >> 8, k = j & 255;
        g_Wqt[j] = __float2half(Wq[k * 768 + n]);
    } else if (idx < SEG3) {
        int j = idx - SEG2;
        int n = j >> 8, k = j & 255;
        g_Wpt[j] = __float2half(Wp[k * 256 + n]);
    }
}

// ---------- mma helpers ----------
__device__ __forceinline__ void ldmatrix_x4(uint32_t* r, uint32_t addr) {
    asm volatile("ldmatrix.sync.aligned.m8n8.x4.shared.b16 {%0,%1,%2,%3}, [%4];"
                 : "=r"(r[0]), "=r"(r[1]), "=r"(r[2]), "=r"(r[3]) : "r"(addr));
}
__device__ __forceinline__ void mma16816(float* c, const uint32_t* a, uint32_t b0, uint32_t b1) {
    asm volatile("mma.sync.aligned.m16n8k16.row.col.f32.f16.f16.f32 "
                 "{%0,%1,%2,%3}, {%4,%5,%6,%7}, {%8,%9}, {%0,%1,%2,%3};"
                 : "+f"(c[0]), "+f"(c[1]), "+f"(c[2]), "+f"(c[3])
                 : "r"(a[0]), "r"(a[1]), "r"(a[2]), "r"(a[3]), "r"(b0), "r"(b1));
}
__device__ __forceinline__ void cp_async16(uint32_t dst, const void* src) {
    asm volatile("cp.async.cg.shared.global [%0], [%1], 16;" :: "r"(dst), "l"(src));
}
__device__ __forceinline__ void cp_commit() { asm volatile("cp.async.commit_group;"); }
template<int N> __device__ __forceinline__ void cp_wait() {
    asm volatile("cp.async.wait_group %0;" :: "n"(N) : "memory");
}

// ---------- GEMM: D[128x64] = A[128x256] @ B[64x256]^T, fp16, 3-stage (R13 config) ----------
#define A_TILE_B 18432
#define STAGE_B  27648
#define GEMM_SMEM (3*STAGE_B)

__global__ void __launch_bounds__(256, 2) gemm_mma(int mode, const float* __restrict__ bias,
                                                   float* __restrict__ out) {
    extern __shared__ __align__(16) __half smg[];
    const uint32_t sb = (uint32_t)__cvta_generic_to_shared(smg);

    const int tid = threadIdx.x, wid = tid >> 5, lane = tid & 31;
    const int warp_m = wid & 3, warp_n = wid >> 2;
    const int mBase = blockIdx.y * 128, nBase = blockIdx.x * 64;

    const __half* A = mode ? g_attn : g_Xh;
    const __half* B = mode ? g_Wpt  : g_Wqt;

    float acc[2][4][4];
#pragma unroll
    for (int i = 0; i < 2; i++)
#pragma unroll
        for (int j = 0; j < 4; j++)
#pragma unroll
            for (int k = 0; k < 4; k++) acc[i][j][k] = 0.f;

    uint32_t aoff[2], boff[2];
#pragma unroll
    for (int mi = 0; mi < 2; mi++)
        aoff[mi] = (uint32_t)(((warp_m * 32 + mi * 16 + (lane & 15)) * 72 + ((lane >> 4) << 3)) * 2);
#pragma unroll
    for (int np = 0; np < 2; np++)
        boff[np] = (uint32_t)(((warp_n * 32 + np * 16 + ((lane >> 4) << 3) + (lane & 7)) * 72 +
                               (((lane >> 3) & 1) << 3)) * 2);

    const int lkc = (tid & 7) << 3;

    auto issue = [&](int c) {
        const uint32_t s0 = sb + (uint32_t)(c % 3) * STAGE_B;
        const int kb = c * 64 + lkc;
#pragma unroll
        for (int t = 0; t < 4; t++) {
            int r = (t * 256 + tid) >> 3;
            cp_async16(s0 + (uint32_t)((r * 72 + lkc) * 2),
                       A + (size_t)(mBase + r) * 256 + kb);
        }
#pragma unroll
        for (int t = 0; t < 2; t++) {
            int r = (t * 256 + tid) >> 3;
            cp_async16(s0 + A_TILE_B + (uint32_t)((r * 72 + lkc) * 2),
                       B + (size_t)(nBase + r) * 256 + kb);
        }
        cp_commit();
    };

    issue(0); issue(1); issue(2);

    for (int c = 0; c < 4; c++) {
        if (c <= 1) cp_wait<2>(); else if (c == 2) cp_wait<1>(); else cp_wait<0>();
        __syncthreads();

        const uint32_t su = sb + (uint32_t)(c % 3) * STAGE_B;
#pragma unroll
        for (int kk = 0; kk < 4; kk++) {
            const uint32_t ko = kk * 32;
            uint32_t a[2][4], b[2][4];
#pragma unroll
            for (int mi = 0; mi < 2; mi++) ldmatrix_x4(a[mi], su + aoff[mi] + ko);
#pragma unroll
            for (int np = 0; np < 2; np++) ldmatrix_x4(b[np], su + A_TILE_B + boff[np] + ko);
#pragma unroll
            for (int mi = 0; mi < 2; mi++)
#pragma unroll
                for (int ni = 0; ni < 4; ni++)
                    mma16816(acc[mi][ni], a[mi], b[ni >> 1][(ni & 1) * 2], b[ni >> 1][(ni & 1) * 2 + 1]);
        }
        __syncthreads();
        if (c + 3 < 4) issue(c + 3);
    }

    // ---- epilogue ----
    const float qscale = 0.17677669529663688f;
#pragma unroll
    for (int mi = 0; mi < 2; mi++) {
#pragma unroll
        for (int half = 0; half < 2; half++) {
            int grow = mBase + warp_m * 32 + mi * 16 + (lane >> 2) + half * 8;
            int b = (grow >= NPIX) ? 1 : 0;
            int nr = grow - b * NPIX;
            if (mode == 0) {
#pragma unroll
                for (int ni = 0; ni < 4; ni++) {
                    int gc = nBase + warp_n * 32 + ni * 8 + (lane & 3) * 2;
                    float x0 = acc[mi][ni][half * 2], x1 = acc[mi][ni][half * 2 + 1];
                    int which = gc >> 8;
                    int head = (gc >> 5) & 7;
                    int d0 = gc & 31;
                    size_t base = ((size_t)(b * HEADS + head) * NPIX + nr) * HD + d0;
                    if (which < 2) {
                        int p = d0 >> 1;
                        float cv = g_cos[nr * NPAIR + p], sv = g_sin[nr * NPAIR + p];
                        float o0 = x0 * cv - x1 * sv;
                        float o1 = x1 * cv + x0 * sv;
                        if (which == 0) {
                            *(__half2*)&g_qh[base] = __floats2half2_rn(o0 * qscale, o1 * qscale);
                        } else {
                            *(__half2*)&g_kh[base] = __floats2half2_rn(o0, o1);
                        }
                    } else {
                        *(__half2*)&g_vh[base] = __floats2half2_rn(x0, x1);
                    }
                }
            } else {
#pragma unroll
                for (int ni = 0; ni < 4; ni++) {
                    int gc = nBase + warp_n * 32 + ni * 8 + (lane & 3) * 2;
                    float2 bv = *(const float2*)&bias[gc];
                    *(float2*)&out[(size_t)grow * 256 + gc] =
                        make_float2(acc[mi][ni][half * 2] + bv.x,
                                    acc[mi][ni][half * 2 + 1] + bv.y);
                }
            }
        }
    }
}

// ---------- attention: mma scores + quad-parallel register softmax + smem-half V ----------
// smem (bytes): kh half[7][64][40] @0 (35840) | sp half[56][52] @35840 (5824)
//               qs half[128][40] @41664 (10240) | vs half[7*56*32] @51904 (25088) => 76992
#define KH_OFF 0
#define SP_OFF 35840
#define QS_OFF 41664
#define VS_OFF 51904
#define ATTN_SMEM 76992

__global__ void __launch_bounds__(256, 3) attn_kernel() {
    extern __shared__ __align__(16) char smc[];
    const uint32_t sbase = (uint32_t)__cvta_generic_to_shared(smc);
    __half* kh = (__half*)(smc + KH_OFF);
    __half* sp = (__half*)(smc + SP_OFF);
    __half* qs = (__half*)(smc + QS_OFF);
    __half* vs = (__half*)(smc + VS_OFF);

    const int i  = blockIdx.x;
    const int bh = blockIdx.y;
    const int tid = threadIdx.x, w = tid >> 5, lane = tid & 31;
    const int r0 = min(max(i - RAD, 0), HW - WIN);

    // ---- loads ----
    const __half* gk = g_kh + ((size_t)bh * NPIX + r0 * HW) * HD;
    for (int idx = tid; idx < 7 * 56 * 4; idx += 256) {
        int r = idx / 224, rem = idx - r * 224;
        int c = rem >> 2, d8 = (rem & 3) << 3;
        *(uint4*)&kh[(r * 64 + c) * 40 + d8] = *(const uint4*)(gk + (r * 56 + c) * 32 + d8);
    }
    const __half* gvh = g_vh + ((size_t)bh * NPIX + r0 * HW) * HD;
    for (int idx = tid; idx < 7 * 56 * 4; idx += 256) {
        ((uint4*)vs)[idx] = ((const uint4*)gvh)[idx];
    }
    const __half* gq = g_qh + ((size_t)bh * NPIX + i * HW) * HD;
    for (int idx = tid; idx < 56 * 4; idx += 256) {
        int j = idx >> 2, d8 = (idx & 3) << 3;
        int row = (j / 7) * 16 + (j % 7);
        *(uint4*)&qs[row * 40 + d8] = *(const uint4*)(gq + j * 32 + d8);
    }
    __syncthreads();

    // ---- score phase (per warp: 7 queries; window union <= 16 keys) ----
    const int j0 = w * 7;
    const int cbase = min(max(j0 - RAD, 0), HW - WIN);

    uint32_t A0[4], A1[4];
    {
        uint32_t qaddr = sbase + QS_OFF +
            (uint32_t)(((w * 16 + (lane & 15)) * 40 + ((lane >> 4) << 3)) * 2);
        ldmatrix_x4(A0, qaddr);
        ldmatrix_x4(A1, qaddr + 32);
    }
    const int qr = lane >> 2;
    const bool qok = (qr < 7);
    const int j = j0 + (qok ? qr : 6);
    const int c0j = min(max(j - RAD, 0), HW - WIN);
    const int lo = c0j - cbase;

    float S[7][2][2];
#pragma unroll
    for (int r = 0; r < 7; r++) {
#pragma unroll
        for (int nt = 0; nt < 2; nt++) {
            uint32_t b[4];
            uint32_t kaddr = sbase + KH_OFF +
                (uint32_t)((((r * 64 + cbase + nt * 8 + (lane & 7)) * 40 + ((lane >> 3) << 3)) * 2));
            ldmatrix_x4(b, kaddr);
            float c4[4] = {0.f, 0.f, 0.f, 0.f};
            mma16816(c4, A0, b[0], b[1]);
            mma16816(c4, A1, b[2], b[3]);
            S[r][nt][0] = c4[0];
            S[r][nt][1] = c4[1];
        }
    }

    // ---- quad-parallel softmax in registers ----
    bool vm[2][2];
    int kcv[2][2];
#pragma unroll
    for (int nt = 0; nt < 2; nt++)
#pragma unroll
        for (int e = 0; e < 2; e++) {
            int col = nt * 8 + ((lane & 3) << 1) + e;
            int kc = col - lo;
            vm[nt][e] = qok && (kc >= 0) && (kc < 7);
            kcv[nt][e] = kc;
        }

    float mx = -1e30f;
#pragma unroll
    for (int r = 0; r < 7; r++)
#pragma unroll
        for (int nt = 0; nt < 2; nt++)
#pragma unroll
            for (int e = 0; e < 2; e++)
                if (vm[nt][e]) mx = fmaxf(mx, S[r][nt][e]);
    mx = fmaxf(mx, __shfl_xor_sync(0xffffffffu, mx, 1));
    mx = fmaxf(mx, __shfl_xor_sync(0xffffffffu, mx, 2));

    float ls = 0.f;
#pragma unroll
    for (int r = 0; r < 7; r++)
#pragma unroll
        for (int nt = 0; nt < 2; nt++)
#pragma unroll
            for (int e = 0; e < 2; e++) {
                float p = vm[nt][e] ? __expf(S[r][nt][e] - mx) : 0.f;
                S[r][nt][e] = p;
                ls += p;
            }
    ls += __shfl_xor_sync(0xffffffffu, ls, 1);
    ls += __shfl_xor_sync(0xffffffffu, ls, 2);
    float inv = 1.0f / ls;

#pragma unroll
    for (int r = 0; r < 7; r++)
#pragma unroll
        for (int nt = 0; nt < 2; nt++)
#pragma unroll
            for (int e = 0; e < 2; e++)
                if (vm[nt][e])
                    sp[j * 52 + r * 7 + kcv[nt][e]] = __float2half(S[r][nt][e] * inv);
    __syncwarp();

    // ---- V phase (per warp, own 7 queries; lane = dim) ----
    const int b = bh >> 3, h = bh & 7;

    for (int t = 0; t < 7; t++) {
        const int jt = j0 + t;
        const int c0t = min(max(jt - RAD, 0), HW - WIN);

        float o0 = 0.f, o1 = 0.f;
#pragma unroll
        for (int rr = 0; rr < 7; rr++) {
            const __half* vrow = vs + (rr * HW + c0t) * HD + lane;
            const __half* prow = sp + jt * 52 + rr * 7;
#pragma unroll
            for (int cc = 0; cc < 7; cc++) {
                float pv = __half2float(prow[cc]);
                float vv = __half2float(vrow[cc * HD]);
                if (cc & 1) o1 = fmaf(pv, vv, o1);
                else        o0 = fmaf(pv, vv, o0);
            }
        }
        size_t oi = ((size_t)b * NPIX + i * HW + jt) * CDIM + h * HD + lane;
        g_attn[oi] = __float2half(o0 + o1);
    }
}

// ---------- launch ----------
extern "C" void kernel_launch(void* const* d_in, const int* in_sizes, int n_in,
                              void* d_out, int out_size) {
    const float* x     = (const float*)d_in[0];
    const float* Wqkv  = (const float*)d_in[1];
    const float* Wproj = (const float*)d_in[2];
    const float* bproj = (const float*)d_in[3];
    float* out = (float*)d_out;

    static bool attr_set = false;
    if (!attr_set) {
        cudaFuncSetAttribute(gemm_mma, cudaFuncAttributeMaxDynamicSharedMemorySize, GEMM_SMEM);
        cudaFuncSetAttribute(attn_kernel, cudaFuncAttributeMaxDynamicSharedMemorySize, ATTN_SMEM);
        attr_set = true;
    }

    prep_kernel<<<(SEG3 + 255) / 256, 256>>>(x, Wqkv, Wproj);
    gemm_mma<<<dim3(12, 49), 256, GEMM_SMEM>>>(0, bproj, out);
    attn_kernel<<<dim3(HW, BATCH * HEADS), 256, ATTN_SMEM>>>();
    gemm_mma<<<dim3(4, 49), 256, GEMM_SMEM>>>(1, bproj, out);
}